// round 1
// baseline (speedup 1.0000x reference)
#include <cuda_runtime.h>
#include <math.h>

// Problem constants (fixed by the dataset)
#define B_  4
#define S_  2048
#define D_  1024
#define H_  16
#define DK_ 64      // per-head key/value dim

// Scratch (device globals — no allocation allowed in kernel_launch)
__device__ float g_q[B_ * H_ * S_ * DK_];     // [B,H,S,DK] 32 MB
__device__ float g_k[B_ * H_ * S_ * DK_];     // 32 MB
__device__ float g_v[B_ * H_ * S_ * DK_];     // 32 MB
__device__ float g_attn[B_ * S_ * H_ * DK_];  // [B,S,H*DV] 32 MB

// ---------------------------------------------------------------------------
// Kernel 1: per-head projection  out[b,h,s,k] = sum_d x[b,s,d] * W[h,d,k]
// Block tile: 128 (s) x 64 (k = full DK), BK=16. 256 threads, 8x4 microtile.
// which: 0 -> g_q, 1 -> g_k, 2 -> g_v
// ---------------------------------------------------------------------------
__global__ __launch_bounds__(256) void proj_kernel(const float* __restrict__ x,
                                                   const float* __restrict__ W,
                                                   int which) {
    float* out = (which == 0) ? g_q : (which == 1) ? g_k : g_v;

    const int h  = blockIdx.y;
    const int b  = blockIdx.z;
    const int m0 = blockIdx.x * 128;  // s offset

    const float* xb   = x + (size_t)b * S_ * D_;
    const float* Wh   = W + (size_t)h * D_ * DK_;
    float*       outh = out + (size_t)(b * H_ + h) * S_ * DK_;

    __shared__ float As[16][128];  // [k][m]  (transposed x tile)
    __shared__ float Bs[16][64];   // [k][n]

    const int tid = threadIdx.x;
    const int tx  = tid & 15;   // col group: 4 cols
    const int ty  = tid >> 4;   // row group: 8 rows

    float acc[8][4];
    #pragma unroll
    for (int i = 0; i < 8; i++)
        #pragma unroll
        for (int j = 0; j < 4; j++) acc[i][j] = 0.0f;

    for (int k0 = 0; k0 < D_; k0 += 16) {
        // Load x tile (128 x 16), store transposed
        {
            const int r   = tid >> 2;        // 0..63
            const int kk4 = (tid & 3) * 4;   // 0,4,8,12
            #pragma unroll
            for (int p = 0; p < 2; p++) {
                float4 t = *(const float4*)&xb[(size_t)(m0 + r + p * 64) * D_ + k0 + kk4];
                As[kk4 + 0][r + p * 64] = t.x;
                As[kk4 + 1][r + p * 64] = t.y;
                As[kk4 + 2][r + p * 64] = t.z;
                As[kk4 + 3][r + p * 64] = t.w;
            }
        }
        // Load W tile (16 x 64), direct
        {
            const int kk = tid >> 4;          // 0..15
            const int c  = (tid & 15) * 4;    // 0..60
            *(float4*)&Bs[kk][c] = *(const float4*)&Wh[(size_t)(k0 + kk) * DK_ + c];
        }
        __syncthreads();

        #pragma unroll
        for (int kk = 0; kk < 16; kk++) {
            float a[8], bb[4];
            *(float4*)&a[0] = *(const float4*)&As[kk][ty * 8];
            *(float4*)&a[4] = *(const float4*)&As[kk][ty * 8 + 4];
            *(float4*)&bb[0] = *(const float4*)&Bs[kk][tx * 4];
            #pragma unroll
            for (int i = 0; i < 8; i++)
                #pragma unroll
                for (int j = 0; j < 4; j++)
                    acc[i][j] = fmaf(a[i], bb[j], acc[i][j]);
        }
        __syncthreads();
    }

    #pragma unroll
    for (int i = 0; i < 8; i++) {
        const int r = m0 + ty * 8 + i;
        *(float4*)&outh[(size_t)r * DK_ + tx * 4] = *(float4*)&acc[i][0];
    }
}

// ---------------------------------------------------------------------------
// Kernel 2: flash attention per (b,h). Block handles 64 q-rows, streams key
// tiles of 64. 256 threads; 4x4 microtiles for both GEMMs. smem = 48 KB.
// KPs buffer is reused: K-phase [d][t], then P-phase [t][q].
// ---------------------------------------------------------------------------
__global__ __launch_bounds__(256) void flash_kernel(float* __restrict__ dummy_unused) {
    const int h  = blockIdx.y;
    const int b  = blockIdx.z;
    const int q0 = blockIdx.x * 64;

    const size_t bh = (size_t)(b * H_ + h) * S_;
    const float* qh = g_q + bh * DK_;
    const float* kh = g_k + bh * DK_;
    const float* vh = g_v + bh * DK_;

    __shared__ float Qs[64][64];   // [d][q]  (Q transposed)
    __shared__ float KPs[64][64];  // K phase: [d][t]; P phase: [t][q]
    __shared__ float Vs[64][64];   // [t][dv]

    const int tid = threadIdx.x;
    const int tx  = tid & 15;   // 4 cols (t in gemm1, dv in gemm2)
    const int ty  = tid >> 4;   // 4 rows (q)

    // Load Q tile transposed: each thread handles one row chunk
    {
        const int r  = tid >> 2;         // 0..63 (q row)
        const int d4 = (tid & 3) * 16;   // dim chunk
        #pragma unroll
        for (int p = 0; p < 4; p++) {
            float4 t = *(const float4*)&qh[(size_t)(q0 + r) * DK_ + d4 + p * 4];
            Qs[d4 + p * 4 + 0][r] = t.x;
            Qs[d4 + p * 4 + 1][r] = t.y;
            Qs[d4 + p * 4 + 2][r] = t.z;
            Qs[d4 + p * 4 + 3][r] = t.w;
        }
    }

    float O[4][4];
    float m_i[4], l_i[4];
    #pragma unroll
    for (int i = 0; i < 4; i++) {
        m_i[i] = -INFINITY;
        l_i[i] = 0.0f;
        #pragma unroll
        for (int j = 0; j < 4; j++) O[i][j] = 0.0f;
    }

    const float scale = 0.125f;  // 1/sqrt(64)

    for (int t0 = 0; t0 < S_; t0 += 64) {
        __syncthreads();  // prev GEMM2 done reading KPs/Vs; Q load visible (1st iter)
        // Load K tile transposed [d][t] and V tile direct [t][dv]
        {
            const int t  = tid >> 2;
            const int d4 = (tid & 3) * 16;
            #pragma unroll
            for (int p = 0; p < 4; p++) {
                float4 kk = *(const float4*)&kh[(size_t)(t0 + t) * DK_ + d4 + p * 4];
                KPs[d4 + p * 4 + 0][t] = kk.x;
                KPs[d4 + p * 4 + 1][t] = kk.y;
                KPs[d4 + p * 4 + 2][t] = kk.z;
                KPs[d4 + p * 4 + 3][t] = kk.w;
                *(float4*)&Vs[t][d4 + p * 4] =
                    *(const float4*)&vh[(size_t)(t0 + t) * DK_ + d4 + p * 4];
            }
        }
        __syncthreads();

        // GEMM1: s[q][t] = Q @ K^T
        float s[4][4];
        #pragma unroll
        for (int i = 0; i < 4; i++)
            #pragma unroll
            for (int j = 0; j < 4; j++) s[i][j] = 0.0f;

        #pragma unroll
        for (int dd = 0; dd < 64; dd++) {
            float a[4], bb[4];
            *(float4*)&a[0]  = *(const float4*)&Qs[dd][ty * 4];
            *(float4*)&bb[0] = *(const float4*)&KPs[dd][tx * 4];
            #pragma unroll
            for (int i = 0; i < 4; i++)
                #pragma unroll
                for (int j = 0; j < 4; j++)
                    s[i][j] = fmaf(a[i], bb[j], s[i][j]);
        }

        // Online softmax update (row reductions across the 16 tx lanes)
        float p[4][4], alpha[4];
        #pragma unroll
        for (int i = 0; i < 4; i++) {
            float mx = fmaxf(fmaxf(s[i][0], s[i][1]), fmaxf(s[i][2], s[i][3])) * scale;
            #pragma unroll
            for (int off = 8; off >= 1; off >>= 1)
                mx = fmaxf(mx, __shfl_xor_sync(0xffffffffu, mx, off));
            const float mnew = fmaxf(m_i[i], mx);
            alpha[i] = __expf(m_i[i] - mnew);
            float rs = 0.0f;
            #pragma unroll
            for (int j = 0; j < 4; j++) {
                p[i][j] = __expf(s[i][j] * scale - mnew);
                rs += p[i][j];
            }
            #pragma unroll
            for (int off = 8; off >= 1; off >>= 1)
                rs += __shfl_xor_sync(0xffffffffu, rs, off);
            l_i[i] = l_i[i] * alpha[i] + rs;
            m_i[i] = mnew;
        }

        __syncthreads();  // everyone done reading KPs as K

        // Write P into KPs as [t][q]; rescale O
        #pragma unroll
        for (int i = 0; i < 4; i++) {
            #pragma unroll
            for (int j = 0; j < 4; j++) {
                KPs[tx * 4 + j][ty * 4 + i] = p[i][j];
                O[i][j] *= alpha[i];
            }
        }
        __syncthreads();

        // GEMM2: O[q][dv] += P @ V
        #pragma unroll
        for (int tt = 0; tt < 64; tt++) {
            float a[4], bb[4];
            *(float4*)&a[0]  = *(const float4*)&KPs[tt][ty * 4];
            *(float4*)&bb[0] = *(const float4*)&Vs[tt][tx * 4];
            #pragma unroll
            for (int i = 0; i < 4; i++)
                #pragma unroll
                for (int j = 0; j < 4; j++)
                    O[i][j] = fmaf(a[i], bb[j], O[i][j]);
        }
    }

    // Epilogue: normalize and write to concat layout [B,S,H*DV]
    #pragma unroll
    for (int i = 0; i < 4; i++) {
        const float inv = 1.0f / l_i[i];
        float4 r;
        r.x = O[i][0] * inv; r.y = O[i][1] * inv;
        r.z = O[i][2] * inv; r.w = O[i][3] * inv;
        const int row = q0 + ty * 4 + i;
        *(float4*)&g_attn[(size_t)(b * S_ + row) * (H_ * DK_) + h * DK_ + tx * 4] = r;
    }
}

// ---------------------------------------------------------------------------
// Kernel 3: output projection  out = g_attn[8192,1024] @ W_O[1024,1024]
// Block tile 128x128, BK=16, 256 threads, 8x8 microtile.
// ---------------------------------------------------------------------------
__global__ __launch_bounds__(256) void outproj_kernel(const float* __restrict__ WO,
                                                      float* __restrict__ out) {
    const int m0 = blockIdx.x * 128;
    const int n0 = blockIdx.y * 128;

    __shared__ float As[16][128];  // [k][m] (transposed attn tile)
    __shared__ float Bs[16][128];  // [k][n]

    const int tid = threadIdx.x;
    const int tx  = tid & 15;   // 8 cols
    const int ty  = tid >> 4;   // 8 rows

    float acc[8][8];
    #pragma unroll
    for (int i = 0; i < 8; i++)
        #pragma unroll
        for (int j = 0; j < 8; j++) acc[i][j] = 0.0f;

    const int NCOL = H_ * DK_;  // 1024

    for (int k0 = 0; k0 < NCOL; k0 += 16) {
        {
            const int r   = tid >> 2;
            const int kk4 = (tid & 3) * 4;
            #pragma unroll
            for (int p = 0; p < 2; p++) {
                float4 t = *(const float4*)&g_attn[(size_t)(m0 + r + p * 64) * NCOL + k0 + kk4];
                As[kk4 + 0][r + p * 64] = t.x;
                As[kk4 + 1][r + p * 64] = t.y;
                As[kk4 + 2][r + p * 64] = t.z;
                As[kk4 + 3][r + p * 64] = t.w;
            }
        }
        {
            #pragma unroll
            for (int p = 0; p < 2; p++) {
                const int idx = tid + p * 256;
                const int kk  = idx >> 5;         // 0..15
                const int c   = (idx & 31) * 4;   // 0..124
                *(float4*)&Bs[kk][c] = *(const float4*)&WO[(size_t)(k0 + kk) * D_ + n0 + c];
            }
        }
        __syncthreads();

        #pragma unroll
        for (int kk = 0; kk < 16; kk++) {
            float a[8], bb[8];
            *(float4*)&a[0]  = *(const float4*)&As[kk][ty * 8];
            *(float4*)&a[4]  = *(const float4*)&As[kk][ty * 8 + 4];
            *(float4*)&bb[0] = *(const float4*)&Bs[kk][tx * 8];
            *(float4*)&bb[4] = *(const float4*)&Bs[kk][tx * 8 + 4];
            #pragma unroll
            for (int i = 0; i < 8; i++)
                #pragma unroll
                for (int j = 0; j < 8; j++)
                    acc[i][j] = fmaf(a[i], bb[j], acc[i][j]);
        }
        __syncthreads();
    }

    #pragma unroll
    for (int i = 0; i < 8; i++) {
        const int r = m0 + ty * 8 + i;
        *(float4*)&out[(size_t)r * D_ + n0 + tx * 8]     = *(float4*)&acc[i][0];
        *(float4*)&out[(size_t)r * D_ + n0 + tx * 8 + 4] = *(float4*)&acc[i][4];
    }
}

// ---------------------------------------------------------------------------
extern "C" void kernel_launch(void* const* d_in, const int* in_sizes, int n_in,
                              void* d_out, int out_size) {
    const float* x  = (const float*)d_in[0];
    const float* wq = (const float*)d_in[1];
    const float* wk = (const float*)d_in[2];
    const float* wv = (const float*)d_in[3];
    const float* wo = (const float*)d_in[4];
    float* out = (float*)d_out;

    dim3 gp(S_ / 128, H_, B_);     // 16,16,4
    proj_kernel<<<gp, 256>>>(x, wq, 0);
    proj_kernel<<<gp, 256>>>(x, wk, 1);
    proj_kernel<<<gp, 256>>>(x, wv, 2);

    dim3 gf(S_ / 64, H_, B_);      // 32,16,4
    flash_kernel<<<gf, 256>>>(nullptr);

    dim3 go((B_ * S_) / 128, D_ / 128);  // 64,8
    outproj_kernel<<<go, 256>>>(wo, out);
}